// round 15
// baseline (speedup 1.0000x reference)
#include <cuda_runtime.h>
#include <cuda_bf16.h>
#include <math.h>
#include <cstdint>

// Problem constants
#define N 4096
#define D 256
#define H 4
#define LOG2E 1.4426950408889634f
#define KSPLIT 8

// ---------------- device scratch ----------------
__device__ float g_h[N * D];                    // h fp32 (4 MB)
__device__ __nv_bfloat16 g_hb[N * D];           // h bf16 row-major (2 MB)
__device__ float g_s1L[N * H];                  // s1 * log2e
__device__ float g_s2L[N * H];                  // s2 * log2e
__device__ __nv_bfloat16 g_Wb[(size_t)N * N];   // head-folded weights bf16 (32 MB)
__device__ float g_Op[KSPLIT * N * D];          // split-K partials (32 MB)
__device__ int g_cnt[32];                       // per-m-tile arrival counters (self-resetting)

// Degree-3 Chebyshev-economized poly for e^{u-1} on u in [0,1] (max abs err ~2e-4)
#define Q0 0.36770f
#define Q1 0.37378f
#define Q2 0.15565f
#define Q3 0.102688f

// ---------------- helpers ----------------
__device__ __forceinline__ float ex2f(float x) {
    float r;
    asm("ex2.approx.ftz.f32 %0, %1;" : "=f"(r) : "f"(x));
    return r;
}
__device__ __forceinline__ uint32_t smem_u32(const void* p) {
    uint32_t a;
    asm("{ .reg .u64 t; cvta.to.shared.u64 t, %1; cvt.u32.u64 %0, t; }" : "=r"(a) : "l"(p));
    return a;
}
__device__ __forceinline__ uint32_t sw128(uint32_t off) {
    return off ^ ((off >> 3) & 0x70);
}
__device__ __forceinline__ void cp_async16(uint32_t dst, const void* src) {
    asm volatile("cp.async.cg.shared.global [%0], [%1], 16;" :: "r"(dst), "l"(src) : "memory");
}
#define CP_COMMIT() asm volatile("cp.async.commit_group;" ::: "memory")
#define CP_WAIT(n)  asm volatile("cp.async.wait_group %0;" :: "n"(n) : "memory")

__device__ __forceinline__ int4 ldcs_int4(const int4* p) {
    int4 v;
    asm volatile("ld.global.cs.v4.s32 {%0,%1,%2,%3}, [%4];"
                 : "=r"(v.x), "=r"(v.y), "=r"(v.z), "=r"(v.w) : "l"(p));
    return v;
}

__device__ __forceinline__ void ldsm_x4(uint32_t addr, uint32_t* r) {
    asm volatile("ldmatrix.sync.aligned.m8n8.x4.shared.b16 {%0,%1,%2,%3}, [%4];"
                 : "=r"(r[0]), "=r"(r[1]), "=r"(r[2]), "=r"(r[3]) : "r"(addr));
}
__device__ __forceinline__ void ldsm_x4_t(uint32_t addr, uint32_t* r) {
    asm volatile("ldmatrix.sync.aligned.m8n8.x4.trans.shared.b16 {%0,%1,%2,%3}, [%4];"
                 : "=r"(r[0]), "=r"(r[1]), "=r"(r[2]), "=r"(r[3]) : "r"(addr));
}
__device__ __forceinline__ void mma_bf16(float* c, const uint32_t* a, const uint32_t* b) {
    asm volatile("mma.sync.aligned.m16n8k16.row.col.f32.bf16.bf16.f32 "
                 "{%0,%1,%2,%3}, {%4,%5,%6,%7}, {%8,%9}, {%0,%1,%2,%3};"
                 : "+f"(c[0]), "+f"(c[1]), "+f"(c[2]), "+f"(c[3])
                 : "r"(a[0]), "r"(a[1]), "r"(a[2]), "r"(a[3]), "r"(b[0]), "r"(b[1]));
}

// ---------------- kernel 1: h, hb(bf16), s1L, s2L --------------------------
__global__ void k_prep(const float* __restrict__ x,
                       const float* __restrict__ cw,
                       const float* __restrict__ cb,
                       const float* __restrict__ a) {
    int i = blockIdx.x;
    int d = threadIdx.x;                     // 256 threads = D
    int lane = d & 31, warp = d >> 5;
    float hv = x[(size_t)i * D + d] * cw[0] + cb[0];
    g_h[(size_t)i * D + d] = hv;
    g_hb[(size_t)i * D + d] = __float2bfloat16_rn(hv);

    float p[8];
    #pragma unroll
    for (int hh = 0; hh < H; hh++) {
        p[hh]     = hv * a[hh * (2 * D) + d];
        p[hh + 4] = hv * a[hh * (2 * D) + D + d];
    }
    #pragma unroll
    for (int s = 16; s > 0; s >>= 1)
        #pragma unroll
        for (int k = 0; k < 8; k++)
            p[k] += __shfl_down_sync(0xFFFFFFFFu, p[k], s);

    __shared__ float ws[8][8];
    if (lane == 0)
        #pragma unroll
        for (int k = 0; k < 8; k++) ws[warp][k] = p[k];
    __syncthreads();
    if (d < 8) {
        float s = 0.f;
        #pragma unroll
        for (int w = 0; w < 8; w++) s += ws[w][d];
        if (d < 4) g_s1L[i * H + d] = s * LOG2E;
        else       g_s2L[i * H + (d - 4)] = s * LOG2E;
    }
}

// ---------------- kernel 2: masked softmax weights, head-folded, bf16 out --
__global__ void __launch_bounds__(256) k_row(const int* __restrict__ adj) {
    __shared__ float zw[8][4];
    __shared__ float iZs[H];

    int i = blockIdx.x;
    int tid = threadIdx.x;
    int lane = tid & 31, warp = tid >> 5;

    float s1L0 = g_s1L[i * H + 0];
    float s1L1 = g_s1L[i * H + 1];
    float s1L2 = g_s1L[i * H + 2];
    float s1L3 = g_s1L[i * H + 3];

    const float4* s2L4 = (const float4*)g_s2L;
    const int4* arow4 = (const int4*)(adj + (size_t)i * N);

    int4 m4[4];
    #pragma unroll
    for (int it = 0; it < 4; it++)
        m4[it] = ldcs_int4(&arow4[(it * 1024 + tid * 4) >> 2]);

    uint2 w16[16];
    float Z0 = 0.f, Z1 = 0.f, Z2 = 0.f, Z3 = 0.f;
    #pragma unroll
    for (int it = 0; it < 4; it++) {
        int jb = it * 1024 + tid * 4;
        #pragma unroll
        for (int q = 0; q < 4; q++) {
            float4 s2 = __ldg(&s2L4[jb + q]);
            int msk = (q == 0) ? m4[it].x : (q == 1) ? m4[it].y
                    : (q == 2) ? m4[it].z : m4[it].w;
            float tl[4] = { s1L0 + s2.x, s1L1 + s2.y, s1L2 + s2.z, s1L3 + s2.w };
            float w[4];
            #pragma unroll
            for (int hh = 0; hh < 4; hh++) {
                float u = ex2f(tl[hh]);
                float pp = fmaf(Q3, u, Q2);
                pp = fmaf(pp, u, Q1);
                pp = fmaf(pp, u, Q0);
                w[hh] = (u > 1.f) ? u : pp;
                if (msk <= 0) w[hh] = 0.f;
            }
            Z0 += w[0]; Z1 += w[1]; Z2 += w[2]; Z3 += w[3];
            __nv_bfloat162 lo = __floats2bfloat162_rn(w[0], w[1]);
            __nv_bfloat162 hi = __floats2bfloat162_rn(w[2], w[3]);
            w16[it * 4 + q] = make_uint2(*(uint32_t*)&lo, *(uint32_t*)&hi);
        }
    }

    #pragma unroll
    for (int s = 16; s > 0; s >>= 1) {
        Z0 += __shfl_down_sync(0xFFFFFFFFu, Z0, s);
        Z1 += __shfl_down_sync(0xFFFFFFFFu, Z1, s);
        Z2 += __shfl_down_sync(0xFFFFFFFFu, Z2, s);
        Z3 += __shfl_down_sync(0xFFFFFFFFu, Z3, s);
    }
    if (lane == 0) { zw[warp][0] = Z0; zw[warp][1] = Z1; zw[warp][2] = Z2; zw[warp][3] = Z3; }
    __syncthreads();
    if (tid < 4) {
        float z = 0.f;
        #pragma unroll
        for (int w = 0; w < 8; w++) z += zw[w][tid];
        iZs[tid] = 0.25f / fmaxf(z, 1e-30f);
    }
    __syncthreads();

    float i0 = iZs[0], i1 = iZs[1], i2 = iZs[2], i3 = iZs[3];
    __nv_bfloat16* Wrow = g_Wb + (size_t)i * N;
    #pragma unroll
    for (int it = 0; it < 4; it++) {
        int jb = it * 1024 + tid * 4;
        float o[4];
        #pragma unroll
        for (int q = 0; q < 4; q++) {
            uint2 pk = w16[it * 4 + q];
            float2 lo = __bfloat1622float2(*(__nv_bfloat162*)&pk.x);
            float2 hi = __bfloat1622float2(*(__nv_bfloat162*)&pk.y);
            o[q] = lo.x * i0 + lo.y * i1 + hi.x * i2 + hi.y * i3;
        }
        __nv_bfloat162 o01 = __floats2bfloat162_rn(o[0], o[1]);
        __nv_bfloat162 o23 = __floats2bfloat162_rn(o[2], o[3]);
        *(uint2*)&Wrow[jb] = make_uint2(*(uint32_t*)&o01, *(uint32_t*)&o23);
    }
}

// ---------------- kernel 3: GEMM + fused split-K reduce + finalize --------
#define BM 128
#define BN 64
#define BK 64
#define ABYTES (BM * BK * 2)                // 16384
#define BBYTES (BK * BN * 2)                // 8192
#define NST (N / BK / KSPLIT)               // 8 stages per CTA

__device__ __forceinline__ void gemm_load(uint32_t aB, uint32_t bB,
                                          int m0, int n0, int k0, int tid) {
    const char* Ap = (const char*)g_Wb;
    const char* Bp = (const char*)g_hb;
    #pragma unroll
    for (int t = 0; t < 4; t++) {
        int idx = tid + t * 256;
        int row = idx >> 3, ch = (idx & 7) * 16;
        cp_async16(aB + sw128(row * 128 + ch),
                   Ap + ((size_t)(m0 + row) * N + k0) * 2 + ch);
    }
    #pragma unroll
    for (int t = 0; t < 2; t++) {
        int idx = tid + t * 256;
        int row = idx >> 3, ch = (idx & 7) * 16;
        cp_async16(bB + sw128(row * 128 + ch),
                   Bp + ((size_t)(k0 + row) * D + n0) * 2 + ch);
    }
}

__global__ void __launch_bounds__(256) k_gemm_mma(const float* __restrict__ bias,
                                                  float* __restrict__ out) {
    extern __shared__ __align__(16) char dsm[];
    uint32_t base = smem_u32(dsm);
    uint32_t aT[3], bT[3];
    #pragma unroll
    for (int s = 0; s < 3; s++) {
        aT[s] = base + s * (ABYTES + BBYTES);
        bT[s] = aT[s] + ABYTES;
    }

    int tid = threadIdx.x;
    int lane = tid & 31, wid = tid >> 5;
    int wm = (wid & 3) * 32;
    int wn = (wid >> 2) * 32;
    int n0 = blockIdx.x * BN;
    int m0 = blockIdx.y * BM;
    int kb = blockIdx.z * (N / KSPLIT);
    float* Oo = g_Op + (size_t)blockIdx.z * N * D;

    int lrow = lane & 15;
    int lcol = (lane >> 4) * 16;
    uint32_t swzA[2], swzB[2];
    #pragma unroll
    for (int mt = 0; mt < 2; mt++)
        swzA[mt] = sw128((uint32_t)((wm + mt * 16 + lrow) * 128 + lcol));
    #pragma unroll
    for (int nt2 = 0; nt2 < 2; nt2++)
        swzB[nt2] = sw128((uint32_t)(lrow * 128 + (wn + nt2 * 16) * 2 + lcol));

    float c[2][4][4];
    #pragma unroll
    for (int mt = 0; mt < 2; mt++)
        #pragma unroll
        for (int nt = 0; nt < 4; nt++)
            #pragma unroll
            for (int q = 0; q < 4; q++) c[mt][nt][q] = 0.f;

    gemm_load(aT[0], bT[0], m0, n0, kb, tid);
    CP_COMMIT();
    gemm_load(aT[1], bT[1], m0, n0, kb + BK, tid);
    CP_COMMIT();

    for (int kc = 0; kc < NST; kc++) {
        int buf = kc % 3;
        if (kc + 1 < NST) { CP_WAIT(1); } else { CP_WAIT(0); }
        __syncthreads();
        if (kc + 2 < NST) {
            gemm_load(aT[(kc + 2) % 3], bT[(kc + 2) % 3], m0, n0, kb + (kc + 2) * BK, tid);
            CP_COMMIT();
        }

        uint32_t afr[2][2][4], bfr[2][4][2];
        uint32_t aTb = aT[buf], bTb = bT[buf];

        #pragma unroll
        for (int mt = 0; mt < 2; mt++)
            ldsm_x4(aTb + swzA[mt], afr[0][mt]);
        #pragma unroll
        for (int nt2 = 0; nt2 < 2; nt2++) {
            uint32_t rr[4];
            ldsm_x4_t(bTb + swzB[nt2], rr);
            bfr[0][nt2 * 2][0] = rr[0]; bfr[0][nt2 * 2][1] = rr[1];
            bfr[0][nt2 * 2 + 1][0] = rr[2]; bfr[0][nt2 * 2 + 1][1] = rr[3];
        }

        #pragma unroll
        for (int ks = 0; ks < 4; ks++) {
            int cur = ks & 1, nxt = cur ^ 1;
            if (ks < 3) {
                int kk = (ks + 1) * 16;
                #pragma unroll
                for (int mt = 0; mt < 2; mt++)
                    ldsm_x4(aTb + (swzA[mt] ^ (uint32_t)(kk << 1)), afr[nxt][mt]);
                #pragma unroll
                for (int nt2 = 0; nt2 < 2; nt2++) {
                    uint32_t rr[4];
                    ldsm_x4_t(bTb + swzB[nt2] + (uint32_t)(kk << 7), rr);
                    bfr[nxt][nt2 * 2][0] = rr[0]; bfr[nxt][nt2 * 2][1] = rr[1];
                    bfr[nxt][nt2 * 2 + 1][0] = rr[2]; bfr[nxt][nt2 * 2 + 1][1] = rr[3];
                }
            }
            #pragma unroll
            for (int mt = 0; mt < 2; mt++)
                #pragma unroll
                for (int nt = 0; nt < 4; nt++)
                    mma_bf16(c[mt][nt], afr[cur][mt], bfr[cur][nt]);
        }
        __syncthreads();
    }

    // store partials
    #pragma unroll
    for (int mt = 0; mt < 2; mt++) {
        int row0 = m0 + wm + mt * 16 + (lane >> 2);
        #pragma unroll
        for (int nt = 0; nt < 4; nt++) {
            int col = n0 + wn + nt * 8 + (lane & 3) * 2;
            *(float2*)&Oo[(size_t)row0 * D + col] = make_float2(c[mt][nt][0], c[mt][nt][1]);
            *(float2*)&Oo[(size_t)(row0 + 8) * D + col] = make_float2(c[mt][nt][2], c[mt][nt][3]);
        }
    }

    // ---- fused split-K reduce + finalize: last CTA of this m-tile does it ----
    __threadfence();                          // release partial stores
    __shared__ int sIsLast;
    __syncthreads();
    if (tid == 0) {
        int old = atomicAdd(&g_cnt[blockIdx.y], 1);
        sIsLast = (old == 4 * KSPLIT - 1);    // 32 producers per m-tile
        if (sIsLast) g_cnt[blockIdx.y] = 0;   // self-reset for next launch
    }
    __syncthreads();
    if (!sIsLast) return;
    __threadfence();                          // acquire side

    // finalize 128 rows [m0, m0+128): warp-per-row, 16 iterations
    #pragma unroll 1
    for (int r = 0; r < 16; r++) {
        int i = m0 + r * 8 + wid;
        int d0 = lane * 8;
        size_t bidx = (size_t)i * D + d0;

        float4 aA = *(const float4*)&g_h[bidx];
        float4 aB = *(const float4*)&g_h[bidx + 4];
        #pragma unroll
        for (int z = 0; z < KSPLIT; z++) {
            const float* Op = g_Op + (size_t)z * N * D;
            float4 oA = *(const float4*)&Op[bidx];
            float4 oB = *(const float4*)&Op[bidx + 4];
            aA.x += oA.x; aA.y += oA.y; aA.z += oA.z; aA.w += oA.w;
            aB.x += oB.x; aB.y += oB.y; aB.z += oB.z; aB.w += oB.w;
        }
        float u[8];
        float va[8] = { aA.x, aA.y, aA.z, aA.w, aB.x, aB.y, aB.z, aB.w };
        float ss = 0.f;
        #pragma unroll
        for (int k = 0; k < 8; k++) {
            float v = 0.5f * va[k];
            u[k] = v > 0.f ? v : expm1f(v);
            ss = fmaf(u[k], u[k], ss);
        }
        #pragma unroll
        for (int s = 16; s > 0; s >>= 1) ss += __shfl_xor_sync(0xFFFFFFFFu, ss, s);
        float inv = 1.f / fmaxf(sqrtf(ss), 1e-12f);

        float4 bA = *(const float4*)&bias[d0];
        float4 bB = *(const float4*)&bias[d0 + 4];
        float bb[8] = { bA.x, bA.y, bA.z, bA.w, bB.x, bB.y, bB.z, bB.w };
        float4 rA, rB;
        rA.x = u[0] * inv + bb[0]; rA.y = u[1] * inv + bb[1];
        rA.z = u[2] * inv + bb[2]; rA.w = u[3] * inv + bb[3];
        rB.x = u[4] * inv + bb[4]; rB.y = u[5] * inv + bb[5];
        rB.z = u[6] * inv + bb[6]; rB.w = u[7] * inv + bb[7];
        *(float4*)&out[bidx] = rA;
        *(float4*)&out[bidx + 4] = rB;
    }
}

// ---------------- launcher ----------------
extern "C" void kernel_launch(void* const* d_in, const int* in_sizes, int n_in,
                              void* d_out, int out_size) {
    const float* x   = (const float*)d_in[0];
    const int*   adj = (const int*)d_in[1];
    const float* cw  = (const float*)d_in[2];
    const float* cb  = (const float*)d_in[3];
    const float* a   = (const float*)d_in[4];
    const float* bias= (const float*)d_in[5];
    float* out = (float*)d_out;

    k_prep<<<N, D>>>(x, cw, cb, a);
    k_row<<<N, 256>>>(adj);

    int smem_gemm = 3 * (ABYTES + BBYTES);       // 73728
    cudaFuncSetAttribute(k_gemm_mma, cudaFuncAttributeMaxDynamicSharedMemorySize, smem_gemm);
    dim3 grid(D / BN, N / BM, KSPLIT);           // (4, 32, 8) = 1024 CTAs
    k_gemm_mma<<<grid, 256, smem_gemm>>>(bias, out);
}

// round 16
// speedup vs baseline: 1.4529x; 1.4529x over previous
#include <cuda_runtime.h>
#include <cuda_bf16.h>
#include <math.h>
#include <cstdint>

// Problem constants
#define N 4096
#define D 256
#define H 4
#define LOG2E 1.4426950408889634f
#define KSPLIT 8

// ---------------- device scratch ----------------
__device__ float g_h[N * D];                    // h fp32 (4 MB)
__device__ __nv_bfloat16 g_hb[N * D];           // h bf16 row-major (2 MB)
__device__ float g_s1L[N * H];                  // s1 * log2e
__device__ float g_s2L[N * H];                  // s2 * log2e
__device__ __nv_bfloat16 g_Wb[(size_t)N * N];   // head-folded weights bf16 (32 MB)
__device__ __nv_bfloat16 g_Opb[(size_t)KSPLIT * N * D];  // split-K partials bf16 (16 MB)

// Degree-3 Chebyshev-economized poly for e^{u-1} on u in [0,1] (max abs err ~2e-4)
#define Q0 0.36770f
#define Q1 0.37378f
#define Q2 0.15565f
#define Q3 0.102688f

// ---------------- helpers ----------------
__device__ __forceinline__ float ex2f(float x) {
    float r;
    asm("ex2.approx.ftz.f32 %0, %1;" : "=f"(r) : "f"(x));
    return r;
}
__device__ __forceinline__ uint32_t smem_u32(const void* p) {
    uint32_t a;
    asm("{ .reg .u64 t; cvta.to.shared.u64 t, %1; cvt.u32.u64 %0, t; }" : "=r"(a) : "l"(p));
    return a;
}
__device__ __forceinline__ uint32_t sw128(uint32_t off) {
    return off ^ ((off >> 3) & 0x70);
}
__device__ __forceinline__ void cp_async16(uint32_t dst, const void* src) {
    asm volatile("cp.async.cg.shared.global [%0], [%1], 16;" :: "r"(dst), "l"(src) : "memory");
}
#define CP_COMMIT() asm volatile("cp.async.commit_group;" ::: "memory")
#define CP_WAIT(n)  asm volatile("cp.async.wait_group %0;" :: "n"(n) : "memory")

__device__ __forceinline__ int4 ldcs_int4(const int4* p) {
    int4 v;
    asm volatile("ld.global.cs.v4.s32 {%0,%1,%2,%3}, [%4];"
                 : "=r"(v.x), "=r"(v.y), "=r"(v.z), "=r"(v.w) : "l"(p));
    return v;
}

__device__ __forceinline__ void ldsm_x4(uint32_t addr, uint32_t* r) {
    asm volatile("ldmatrix.sync.aligned.m8n8.x4.shared.b16 {%0,%1,%2,%3}, [%4];"
                 : "=r"(r[0]), "=r"(r[1]), "=r"(r[2]), "=r"(r[3]) : "r"(addr));
}
__device__ __forceinline__ void ldsm_x4_t(uint32_t addr, uint32_t* r) {
    asm volatile("ldmatrix.sync.aligned.m8n8.x4.trans.shared.b16 {%0,%1,%2,%3}, [%4];"
                 : "=r"(r[0]), "=r"(r[1]), "=r"(r[2]), "=r"(r[3]) : "r"(addr));
}
__device__ __forceinline__ void mma_bf16(float* c, const uint32_t* a, const uint32_t* b) {
    asm volatile("mma.sync.aligned.m16n8k16.row.col.f32.bf16.bf16.f32 "
                 "{%0,%1,%2,%3}, {%4,%5,%6,%7}, {%8,%9}, {%0,%1,%2,%3};"
                 : "+f"(c[0]), "+f"(c[1]), "+f"(c[2]), "+f"(c[3])
                 : "r"(a[0]), "r"(a[1]), "r"(a[2]), "r"(a[3]), "r"(b[0]), "r"(b[1]));
}

// ---------------- kernel 1: h, hb(bf16), s1L, s2L (4 rows/CTA) ------------
__global__ void __launch_bounds__(256) k_prep(const float* __restrict__ x,
                                              const float* __restrict__ cw,
                                              const float* __restrict__ cb,
                                              const float* __restrict__ a) {
    int i0 = blockIdx.x * 4;
    int d = threadIdx.x;                     // 256 threads = D
    int lane = d & 31, warp = d >> 5;

    float cwv = cw[0], cbv = cb[0];

    // a weights for this d (8 values, L2/L1 resident)
    float av[8];
    #pragma unroll
    for (int hh = 0; hh < H; hh++) {
        av[hh]     = a[hh * (2 * D) + d];
        av[hh + 4] = a[hh * (2 * D) + D + d];
    }

    // batched x loads (MLP 4)
    float xv[4];
    #pragma unroll
    for (int r = 0; r < 4; r++)
        xv[r] = x[(size_t)(i0 + r) * D + d];

    float hv[4];
    #pragma unroll
    for (int r = 0; r < 4; r++) {
        hv[r] = xv[r] * cwv + cbv;
        g_h[(size_t)(i0 + r) * D + d] = hv[r];
        g_hb[(size_t)(i0 + r) * D + d] = __float2bfloat16_rn(hv[r]);
    }

    // 32 partial products: p[r*8 + k]
    float p[32];
    #pragma unroll
    for (int r = 0; r < 4; r++)
        #pragma unroll
        for (int k = 0; k < 8; k++)
            p[r * 8 + k] = hv[r] * av[k];

    // butterfly reduce: all lanes end with warp totals (32 independent chains)
    #pragma unroll
    for (int s = 16; s > 0; s >>= 1)
        #pragma unroll
        for (int k = 0; k < 32; k++)
            p[k] += __shfl_xor_sync(0xFFFFFFFFu, p[k], s);

    __shared__ float ws[8][32];
    ws[warp][lane] = p[lane];                // lane m writes value m
    __syncthreads();
    if (d < 32) {
        float s = 0.f;
        #pragma unroll
        for (int w = 0; w < 8; w++) s += ws[w][d];
        int r = d >> 3, kk = d & 7;
        int row = i0 + r;
        if (kk < 4) g_s1L[row * H + kk] = s * LOG2E;
        else        g_s2L[row * H + (kk - 4)] = s * LOG2E;
    }
}

// ---------------- kernel 2: masked softmax weights, head-folded, bf16 out --
__global__ void __launch_bounds__(256) k_row(const int* __restrict__ adj) {
    __shared__ float zw[8][4];
    __shared__ float iZs[H];

    int i = blockIdx.x;
    int tid = threadIdx.x;
    int lane = tid & 31, warp = tid >> 5;

    float s1L0 = g_s1L[i * H + 0];
    float s1L1 = g_s1L[i * H + 1];
    float s1L2 = g_s1L[i * H + 2];
    float s1L3 = g_s1L[i * H + 3];

    const float4* s2L4 = (const float4*)g_s2L;
    const int4* arow4 = (const int4*)(adj + (size_t)i * N);

    int4 m4[4];
    #pragma unroll
    for (int it = 0; it < 4; it++)
        m4[it] = ldcs_int4(&arow4[(it * 1024 + tid * 4) >> 2]);

    uint2 w16[16];
    float Z0 = 0.f, Z1 = 0.f, Z2 = 0.f, Z3 = 0.f;
    #pragma unroll
    for (int it = 0; it < 4; it++) {
        int jb = it * 1024 + tid * 4;
        #pragma unroll
        for (int q = 0; q < 4; q++) {
            float4 s2 = __ldg(&s2L4[jb + q]);
            int msk = (q == 0) ? m4[it].x : (q == 1) ? m4[it].y
                    : (q == 2) ? m4[it].z : m4[it].w;
            float tl[4] = { s1L0 + s2.x, s1L1 + s2.y, s1L2 + s2.z, s1L3 + s2.w };
            float w[4];
            #pragma unroll
            for (int hh = 0; hh < 4; hh++) {
                float u = ex2f(tl[hh]);
                float pp = fmaf(Q3, u, Q2);
                pp = fmaf(pp, u, Q1);
                pp = fmaf(pp, u, Q0);
                w[hh] = (u > 1.f) ? u : pp;
                if (msk <= 0) w[hh] = 0.f;
            }
            Z0 += w[0]; Z1 += w[1]; Z2 += w[2]; Z3 += w[3];
            __nv_bfloat162 lo = __floats2bfloat162_rn(w[0], w[1]);
            __nv_bfloat162 hi = __floats2bfloat162_rn(w[2], w[3]);
            w16[it * 4 + q] = make_uint2(*(uint32_t*)&lo, *(uint32_t*)&hi);
        }
    }

    #pragma unroll
    for (int s = 16; s > 0; s >>= 1) {
        Z0 += __shfl_down_sync(0xFFFFFFFFu, Z0, s);
        Z1 += __shfl_down_sync(0xFFFFFFFFu, Z1, s);
        Z2 += __shfl_down_sync(0xFFFFFFFFu, Z2, s);
        Z3 += __shfl_down_sync(0xFFFFFFFFu, Z3, s);
    }
    if (lane == 0) { zw[warp][0] = Z0; zw[warp][1] = Z1; zw[warp][2] = Z2; zw[warp][3] = Z3; }
    __syncthreads();
    if (tid < 4) {
        float z = 0.f;
        #pragma unroll
        for (int w = 0; w < 8; w++) z += zw[w][tid];
        iZs[tid] = 0.25f / fmaxf(z, 1e-30f);
    }
    __syncthreads();

    float i0 = iZs[0], i1 = iZs[1], i2 = iZs[2], i3 = iZs[3];
    __nv_bfloat16* Wrow = g_Wb + (size_t)i * N;
    #pragma unroll
    for (int it = 0; it < 4; it++) {
        int jb = it * 1024 + tid * 4;
        float o[4];
        #pragma unroll
        for (int q = 0; q < 4; q++) {
            uint2 pk = w16[it * 4 + q];
            float2 lo = __bfloat1622float2(*(__nv_bfloat162*)&pk.x);
            float2 hi = __bfloat1622float2(*(__nv_bfloat162*)&pk.y);
            o[q] = lo.x * i0 + lo.y * i1 + hi.x * i2 + hi.y * i3;
        }
        __nv_bfloat162 o01 = __floats2bfloat162_rn(o[0], o[1]);
        __nv_bfloat162 o23 = __floats2bfloat162_rn(o[2], o[3]);
        *(uint2*)&Wrow[jb] = make_uint2(*(uint32_t*)&o01, *(uint32_t*)&o23);
    }
}

// ---------------- kernel 3: O = W' @ h  via mma.sync bf16, split-K=8 ------
#define BM 128
#define BN 64
#define BK 64
#define ABYTES (BM * BK * 2)                // 16384
#define BBYTES (BK * BN * 2)                // 8192
#define NST (N / BK / KSPLIT)               // 8 stages per CTA

__device__ __forceinline__ void gemm_load(uint32_t aB, uint32_t bB,
                                          int m0, int n0, int k0, int tid) {
    const char* Ap = (const char*)g_Wb;
    const char* Bp = (const char*)g_hb;
    #pragma unroll
    for (int t = 0; t < 4; t++) {
        int idx = tid + t * 256;
        int row = idx >> 3, ch = (idx & 7) * 16;
        cp_async16(aB + sw128(row * 128 + ch),
                   Ap + ((size_t)(m0 + row) * N + k0) * 2 + ch);
    }
    #pragma unroll
    for (int t = 0; t < 2; t++) {
        int idx = tid + t * 256;
        int row = idx >> 3, ch = (idx & 7) * 16;
        cp_async16(bB + sw128(row * 128 + ch),
                   Bp + ((size_t)(k0 + row) * D + n0) * 2 + ch);
    }
}

__global__ void __launch_bounds__(256) k_gemm_mma() {
    extern __shared__ __align__(16) char dsm[];
    uint32_t base = smem_u32(dsm);
    uint32_t aT[3], bT[3];
    #pragma unroll
    for (int s = 0; s < 3; s++) {
        aT[s] = base + s * (ABYTES + BBYTES);
        bT[s] = aT[s] + ABYTES;
    }

    int tid = threadIdx.x;
    int lane = tid & 31, wid = tid >> 5;
    int wm = (wid & 3) * 32;
    int wn = (wid >> 2) * 32;
    int n0 = blockIdx.x * BN;
    int m0 = blockIdx.y * BM;
    int kb = blockIdx.z * (N / KSPLIT);
    __nv_bfloat16* Oo = g_Opb + (size_t)blockIdx.z * N * D;

    int lrow = lane & 15;
    int lcol = (lane >> 4) * 16;
    uint32_t swzA[2], swzB[2];
    #pragma unroll
    for (int mt = 0; mt < 2; mt++)
        swzA[mt] = sw128((uint32_t)((wm + mt * 16 + lrow) * 128 + lcol));
    #pragma unroll
    for (int nt2 = 0; nt2 < 2; nt2++)
        swzB[nt2] = sw128((uint32_t)(lrow * 128 + (wn + nt2 * 16) * 2 + lcol));

    float c[2][4][4];
    #pragma unroll
    for (int mt = 0; mt < 2; mt++)
        #pragma unroll
        for (int nt = 0; nt < 4; nt++)
            #pragma unroll
            for (int q = 0; q < 4; q++) c[mt][nt][q] = 0.f;

    gemm_load(aT[0], bT[0], m0, n0, kb, tid);
    CP_COMMIT();
    gemm_load(aT[1], bT[1], m0, n0, kb + BK, tid);
    CP_COMMIT();

    for (int kc = 0; kc < NST; kc++) {
        int buf = kc % 3;
        if (kc + 1 < NST) { CP_WAIT(1); } else { CP_WAIT(0); }
        __syncthreads();
        if (kc + 2 < NST) {
            gemm_load(aT[(kc + 2) % 3], bT[(kc + 2) % 3], m0, n0, kb + (kc + 2) * BK, tid);
            CP_COMMIT();
        }

        uint32_t afr[2][2][4], bfr[2][4][2];
        uint32_t aTb = aT[buf], bTb = bT[buf];

        #pragma unroll
        for (int mt = 0; mt < 2; mt++)
            ldsm_x4(aTb + swzA[mt], afr[0][mt]);
        #pragma unroll
        for (int nt2 = 0; nt2 < 2; nt2++) {
            uint32_t rr[4];
            ldsm_x4_t(bTb + swzB[nt2], rr);
            bfr[0][nt2 * 2][0] = rr[0]; bfr[0][nt2 * 2][1] = rr[1];
            bfr[0][nt2 * 2 + 1][0] = rr[2]; bfr[0][nt2 * 2 + 1][1] = rr[3];
        }

        #pragma unroll
        for (int ks = 0; ks < 4; ks++) {
            int cur = ks & 1, nxt = cur ^ 1;
            if (ks < 3) {
                int kk = (ks + 1) * 16;
                #pragma unroll
                for (int mt = 0; mt < 2; mt++)
                    ldsm_x4(aTb + (swzA[mt] ^ (uint32_t)(kk << 1)), afr[nxt][mt]);
                #pragma unroll
                for (int nt2 = 0; nt2 < 2; nt2++) {
                    uint32_t rr[4];
                    ldsm_x4_t(bTb + swzB[nt2] + (uint32_t)(kk << 7), rr);
                    bfr[nxt][nt2 * 2][0] = rr[0]; bfr[nxt][nt2 * 2][1] = rr[1];
                    bfr[nxt][nt2 * 2 + 1][0] = rr[2]; bfr[nxt][nt2 * 2 + 1][1] = rr[3];
                }
            }
            #pragma unroll
            for (int mt = 0; mt < 2; mt++)
                #pragma unroll
                for (int nt = 0; nt < 4; nt++)
                    mma_bf16(c[mt][nt], afr[cur][mt], bfr[cur][nt]);
        }
        __syncthreads();
    }

    // epilogue: bf16 packed stores
    #pragma unroll
    for (int mt = 0; mt < 2; mt++) {
        int row0 = m0 + wm + mt * 16 + (lane >> 2);
        #pragma unroll
        for (int nt = 0; nt < 4; nt++) {
            int col = n0 + wn + nt * 8 + (lane & 3) * 2;
            __nv_bfloat162 v0 = __floats2bfloat162_rn(c[mt][nt][0], c[mt][nt][1]);
            __nv_bfloat162 v1 = __floats2bfloat162_rn(c[mt][nt][2], c[mt][nt][3]);
            *(__nv_bfloat162*)&Oo[(size_t)row0 * D + col] = v0;
            *(__nv_bfloat162*)&Oo[(size_t)(row0 + 8) * D + col] = v1;
        }
    }
}

// ---------------- kernel 4: elu(0.5*(ΣO+h)), row-normalize, +bias ---------
__global__ void __launch_bounds__(256) k_final(const float* __restrict__ bias,
                                               float* __restrict__ out) {
    int tid = threadIdx.x;
    int lane = tid & 31, warp = tid >> 5;
    int i = blockIdx.x * 8 + warp;
    int d0 = lane * 8;
    size_t base = (size_t)i * D + d0;

    float acc[8];
    {
        float4 aA = *(const float4*)&g_h[base];
        float4 aB = *(const float4*)&g_h[base + 4];
        acc[0] = aA.x; acc[1] = aA.y; acc[2] = aA.z; acc[3] = aA.w;
        acc[4] = aB.x; acc[5] = aB.y; acc[6] = aB.z; acc[7] = aB.w;
    }
    #pragma unroll
    for (int z = 0; z < KSPLIT; z++) {
        const __nv_bfloat16* Op = g_Opb + (size_t)z * N * D;
        uint4 v = *(const uint4*)&Op[base];          // 8 bf16
        uint32_t vv[4] = { v.x, v.y, v.z, v.w };
        #pragma unroll
        for (int p = 0; p < 4; p++) {
            float2 f = __bfloat1622float2(*(__nv_bfloat162*)&vv[p]);
            acc[p * 2]     += f.x;
            acc[p * 2 + 1] += f.y;
        }
    }
    float u[8];
    float ss = 0.f;
    #pragma unroll
    for (int k = 0; k < 8; k++) {
        float v = 0.5f * acc[k];
        u[k] = v > 0.f ? v : expm1f(v);
        ss = fmaf(u[k], u[k], ss);
    }
    #pragma unroll
    for (int s = 16; s > 0; s >>= 1) ss += __shfl_xor_sync(0xFFFFFFFFu, ss, s);
    float inv = 1.f / fmaxf(sqrtf(ss), 1e-12f);

    float4 bA = *(const float4*)&bias[d0];
    float4 bB = *(const float4*)&bias[d0 + 4];
    float bb[8] = { bA.x, bA.y, bA.z, bA.w, bB.x, bB.y, bB.z, bB.w };
    float4 rA, rB;
    rA.x = u[0] * inv + bb[0]; rA.y = u[1] * inv + bb[1];
    rA.z = u[2] * inv + bb[2]; rA.w = u[3] * inv + bb[3];
    rB.x = u[4] * inv + bb[4]; rB.y = u[5] * inv + bb[5];
    rB.z = u[6] * inv + bb[6]; rB.w = u[7] * inv + bb[7];
    *(float4*)&out[base] = rA;
    *(float4*)&out[base + 4] = rB;
}

// ---------------- launcher ----------------
extern "C" void kernel_launch(void* const* d_in, const int* in_sizes, int n_in,
                              void* d_out, int out_size) {
    const float* x   = (const float*)d_in[0];
    const int*   adj = (const int*)d_in[1];
    const float* cw  = (const float*)d_in[2];
    const float* cb  = (const float*)d_in[3];
    const float* a   = (const float*)d_in[4];
    const float* bias= (const float*)d_in[5];
    float* out = (float*)d_out;

    k_prep<<<N / 4, D>>>(x, cw, cb, a);
    k_row<<<N, 256>>>(adj);

    int smem_gemm = 3 * (ABYTES + BBYTES);       // 73728
    cudaFuncSetAttribute(k_gemm_mma, cudaFuncAttributeMaxDynamicSharedMemorySize, smem_gemm);
    dim3 grid(D / BN, N / BM, KSPLIT);           // (4, 32, 8) = 1024 CTAs
    k_gemm_mma<<<grid, 256, smem_gemm>>>();

    k_final<<<N / 8, 256>>>(bias, out);
}

// round 17
// speedup vs baseline: 1.5666x; 1.0782x over previous
#include <cuda_runtime.h>
#include <cuda_bf16.h>
#include <math.h>
#include <cstdint>

// Problem constants
#define N 4096
#define D 256
#define H 4
#define LOG2E 1.4426950408889634f
#define KSPLIT 8

// ---------------- device scratch ----------------
__device__ float g_h[N * D];                    // h fp32 (4 MB)
__device__ __nv_bfloat16 g_hb[N * D];           // h bf16 row-major (2 MB)
__device__ float g_s1L[N * H];                  // s1 * log2e
__device__ float g_s2L[N * H];                  // s2 * log2e
__device__ __nv_bfloat16 g_Wb[(size_t)N * N];   // head-folded weights bf16 (32 MB)
__device__ __nv_bfloat16 g_Opb[(size_t)KSPLIT * N * D];  // split-K partials bf16 (16 MB)

// Degree-2 poly for e^{u-1} on u in [0,1] (max abs err ~3.2e-3, subdominant
// to bf16 storage quantization)
#define C0 0.370908f
#define C1 0.316028f
#define C2 0.309632f

// ---------------- helpers ----------------
__device__ __forceinline__ float ex2f(float x) {
    float r;
    asm("ex2.approx.ftz.f32 %0, %1;" : "=f"(r) : "f"(x));
    return r;
}
__device__ __forceinline__ uint32_t smem_u32(const void* p) {
    uint32_t a;
    asm("{ .reg .u64 t; cvta.to.shared.u64 t, %1; cvt.u32.u64 %0, t; }" : "=r"(a) : "l"(p));
    return a;
}
__device__ __forceinline__ uint32_t sw128(uint32_t off) {
    return off ^ ((off >> 3) & 0x70);
}
__device__ __forceinline__ void cp_async16(uint32_t dst, const void* src) {
    asm volatile("cp.async.cg.shared.global [%0], [%1], 16;" :: "r"(dst), "l"(src) : "memory");
}
#define CP_COMMIT() asm volatile("cp.async.commit_group;" ::: "memory")
#define CP_WAIT(n)  asm volatile("cp.async.wait_group %0;" :: "n"(n) : "memory")

__device__ __forceinline__ int4 ldcs_int4(const int4* p) {
    int4 v;
    asm volatile("ld.global.cs.v4.s32 {%0,%1,%2,%3}, [%4];"
                 : "=r"(v.x), "=r"(v.y), "=r"(v.z), "=r"(v.w) : "l"(p));
    return v;
}

__device__ __forceinline__ void ldsm_x4(uint32_t addr, uint32_t* r) {
    asm volatile("ldmatrix.sync.aligned.m8n8.x4.shared.b16 {%0,%1,%2,%3}, [%4];"
                 : "=r"(r[0]), "=r"(r[1]), "=r"(r[2]), "=r"(r[3]) : "r"(addr));
}
__device__ __forceinline__ void ldsm_x4_t(uint32_t addr, uint32_t* r) {
    asm volatile("ldmatrix.sync.aligned.m8n8.x4.trans.shared.b16 {%0,%1,%2,%3}, [%4];"
                 : "=r"(r[0]), "=r"(r[1]), "=r"(r[2]), "=r"(r[3]) : "r"(addr));
}
__device__ __forceinline__ void mma_bf16(float* c, const uint32_t* a, const uint32_t* b) {
    asm volatile("mma.sync.aligned.m16n8k16.row.col.f32.bf16.bf16.f32 "
                 "{%0,%1,%2,%3}, {%4,%5,%6,%7}, {%8,%9}, {%0,%1,%2,%3};"
                 : "+f"(c[0]), "+f"(c[1]), "+f"(c[2]), "+f"(c[3])
                 : "r"(a[0]), "r"(a[1]), "r"(a[2]), "r"(a[3]), "r"(b[0]), "r"(b[1]));
}

// ---------------- kernel 1: h, hb(bf16), s1L, s2L (4 rows/CTA) ------------
__global__ void __launch_bounds__(256) k_prep(const float* __restrict__ x,
                                              const float* __restrict__ cw,
                                              const float* __restrict__ cb,
                                              const float* __restrict__ a) {
    int i0 = blockIdx.x * 4;
    int d = threadIdx.x;                     // 256 threads = D
    int lane = d & 31, warp = d >> 5;

    float cwv = cw[0], cbv = cb[0];

    float av[8];
    #pragma unroll
    for (int hh = 0; hh < H; hh++) {
        av[hh]     = a[hh * (2 * D) + d];
        av[hh + 4] = a[hh * (2 * D) + D + d];
    }

    float xv[4];
    #pragma unroll
    for (int r = 0; r < 4; r++)
        xv[r] = x[(size_t)(i0 + r) * D + d];

    float hv[4];
    #pragma unroll
    for (int r = 0; r < 4; r++) {
        hv[r] = xv[r] * cwv + cbv;
        g_h[(size_t)(i0 + r) * D + d] = hv[r];
        g_hb[(size_t)(i0 + r) * D + d] = __float2bfloat16_rn(hv[r]);
    }

    float p[32];
    #pragma unroll
    for (int r = 0; r < 4; r++)
        #pragma unroll
        for (int k = 0; k < 8; k++)
            p[r * 8 + k] = hv[r] * av[k];

    #pragma unroll
    for (int s = 16; s > 0; s >>= 1)
        #pragma unroll
        for (int k = 0; k < 32; k++)
            p[k] += __shfl_xor_sync(0xFFFFFFFFu, p[k], s);

    __shared__ float ws[8][32];
    ws[warp][lane] = p[lane];
    __syncthreads();
    if (d < 32) {
        float s = 0.f;
        #pragma unroll
        for (int w = 0; w < 8; w++) s += ws[w][d];
        int r = d >> 3, kk = d & 7;
        int row = i0 + r;
        if (kk < 4) g_s1L[row * H + kk] = s * LOG2E;
        else        g_s2L[row * H + (kk - 4)] = s * LOG2E;
    }
}

// ---------------- kernel 2: masked softmax weights, head-folded, bf16 out --
__global__ void __launch_bounds__(256) k_row(const int* __restrict__ adj) {
    __shared__ float zw[8][4];
    __shared__ float iZs[H];

    int i = blockIdx.x;
    int tid = threadIdx.x;
    int lane = tid & 31, warp = tid >> 5;

    float s1L0 = g_s1L[i * H + 0];
    float s1L1 = g_s1L[i * H + 1];
    float s1L2 = g_s1L[i * H + 2];
    float s1L3 = g_s1L[i * H + 3];

    const float4* s2L4 = (const float4*)g_s2L;
    const int4* arow4 = (const int4*)(adj + (size_t)i * N);

    int4 m4[4];
    #pragma unroll
    for (int it = 0; it < 4; it++)
        m4[it] = ldcs_int4(&arow4[(it * 1024 + tid * 4) >> 2]);

    uint2 w16[16];
    float Z0 = 0.f, Z1 = 0.f, Z2 = 0.f, Z3 = 0.f;
    #pragma unroll
    for (int it = 0; it < 4; it++) {
        int jb = it * 1024 + tid * 4;
        #pragma unroll
        for (int q = 0; q < 4; q++) {
            float4 s2 = __ldg(&s2L4[jb + q]);
            int msk = (q == 0) ? m4[it].x : (q == 1) ? m4[it].y
                    : (q == 2) ? m4[it].z : m4[it].w;
            float tl[4] = { s1L0 + s2.x, s1L1 + s2.y, s1L2 + s2.z, s1L3 + s2.w };
            float w[4];
            #pragma unroll
            for (int hh = 0; hh < 4; hh++) {
                float u = ex2f(tl[hh]);
                float pp = fmaf(C2, u, C1);
                pp = fmaf(pp, u, C0);
                w[hh] = (u > 1.f) ? u : pp;
                if (msk <= 0) w[hh] = 0.f;
            }
            Z0 += w[0]; Z1 += w[1]; Z2 += w[2]; Z3 += w[3];
            __nv_bfloat162 lo = __floats2bfloat162_rn(w[0], w[1]);
            __nv_bfloat162 hi = __floats2bfloat162_rn(w[2], w[3]);
            w16[it * 4 + q] = make_uint2(*(uint32_t*)&lo, *(uint32_t*)&hi);
        }
    }

    #pragma unroll
    for (int s = 16; s > 0; s >>= 1) {
        Z0 += __shfl_down_sync(0xFFFFFFFFu, Z0, s);
        Z1 += __shfl_down_sync(0xFFFFFFFFu, Z1, s);
        Z2 += __shfl_down_sync(0xFFFFFFFFu, Z2, s);
        Z3 += __shfl_down_sync(0xFFFFFFFFu, Z3, s);
    }
    if (lane == 0) { zw[warp][0] = Z0; zw[warp][1] = Z1; zw[warp][2] = Z2; zw[warp][3] = Z3; }
    __syncthreads();
    if (tid < 4) {
        float z = 0.f;
        #pragma unroll
        for (int w = 0; w < 8; w++) z += zw[w][tid];
        iZs[tid] = 0.25f / fmaxf(z, 1e-30f);
    }
    __syncthreads();

    // combine pass in packed bf16x2 (3 ops per 4-head dot)
    __nv_bfloat162 iz01 = __floats2bfloat162_rn(iZs[0], iZs[1]);
    __nv_bfloat162 iz23 = __floats2bfloat162_rn(iZs[2], iZs[3]);
    __nv_bfloat16* Wrow = g_Wb + (size_t)i * N;
    #pragma unroll
    for (int it = 0; it < 4; it++) {
        int jb = it * 1024 + tid * 4;
        __nv_bfloat16 o[4];
        #pragma unroll
        for (int q = 0; q < 4; q++) {
            uint2 pk = w16[it * 4 + q];
            __nv_bfloat162 lo = *(__nv_bfloat162*)&pk.x;
            __nv_bfloat162 hi = *(__nv_bfloat162*)&pk.y;
            __nv_bfloat162 t = __hfma2(hi, iz23, __hmul2(lo, iz01));
            o[q] = __hadd(__low2bfloat16(t), __high2bfloat16(t));
        }
        __nv_bfloat162 o01 = __halves2bfloat162(o[0], o[1]);
        __nv_bfloat162 o23 = __halves2bfloat162(o[2], o[3]);
        *(uint2*)&Wrow[jb] = make_uint2(*(uint32_t*)&o01, *(uint32_t*)&o23);
    }
}

// ---------------- kernel 3: O = W' @ h  via mma.sync bf16, split-K=8 ------
#define BM 128
#define BN 64
#define BK 64
#define ABYTES (BM * BK * 2)                // 16384
#define BBYTES (BK * BN * 2)                // 8192
#define NST (N / BK / KSPLIT)               // 8 stages per CTA

__device__ __forceinline__ void gemm_load(uint32_t aB, uint32_t bB,
                                          int m0, int n0, int k0, int tid) {
    const char* Ap = (const char*)g_Wb;
    const char* Bp = (const char*)g_hb;
    #pragma unroll
    for (int t = 0; t < 4; t++) {
        int idx = tid + t * 256;
        int row = idx >> 3, ch = (idx & 7) * 16;
        cp_async16(aB + sw128(row * 128 + ch),
                   Ap + ((size_t)(m0 + row) * N + k0) * 2 + ch);
    }
    #pragma unroll
    for (int t = 0; t < 2; t++) {
        int idx = tid + t * 256;
        int row = idx >> 3, ch = (idx & 7) * 16;
        cp_async16(bB + sw128(row * 128 + ch),
                   Bp + ((size_t)(k0 + row) * D + n0) * 2 + ch);
    }
}

__global__ void __launch_bounds__(256) k_gemm_mma() {
    extern __shared__ __align__(16) char dsm[];
    uint32_t base = smem_u32(dsm);
    uint32_t aT[3], bT[3];
    #pragma unroll
    for (int s = 0; s < 3; s++) {
        aT[s] = base + s * (ABYTES + BBYTES);
        bT[s] = aT[s] + ABYTES;
    }

    int tid = threadIdx.x;
    int lane = tid & 31, wid = tid >> 5;
    int wm = (wid & 3) * 32;
    int wn = (wid >> 2) * 32;
    int n0 = blockIdx.x * BN;
    int m0 = blockIdx.y * BM;
    int kb = blockIdx.z * (N / KSPLIT);
    __nv_bfloat16* Oo = g_Opb + (size_t)blockIdx.z * N * D;

    int lrow = lane & 15;
    int lcol = (lane >> 4) * 16;
    uint32_t swzA[2], swzB[2];
    #pragma unroll
    for (int mt = 0; mt < 2; mt++)
        swzA[mt] = sw128((uint32_t)((wm + mt * 16 + lrow) * 128 + lcol));
    #pragma unroll
    for (int nt2 = 0; nt2 < 2; nt2++)
        swzB[nt2] = sw128((uint32_t)(lrow * 128 + (wn + nt2 * 16) * 2 + lcol));

    float c[2][4][4];
    #pragma unroll
    for (int mt = 0; mt < 2; mt++)
        #pragma unroll
        for (int nt = 0; nt < 4; nt++)
            #pragma unroll
            for (int q = 0; q < 4; q++) c[mt][nt][q] = 0.f;

    gemm_load(aT[0], bT[0], m0, n0, kb, tid);
    CP_COMMIT();
    gemm_load(aT[1], bT[1], m0, n0, kb + BK, tid);
    CP_COMMIT();

    for (int kc = 0; kc < NST; kc++) {
        int buf = kc % 3;
        if (kc + 1 < NST) { CP_WAIT(1); } else { CP_WAIT(0); }
        __syncthreads();
        if (kc + 2 < NST) {
            gemm_load(aT[(kc + 2) % 3], bT[(kc + 2) % 3], m0, n0, kb + (kc + 2) * BK, tid);
            CP_COMMIT();
        }

        uint32_t afr[2][2][4], bfr[2][4][2];
        uint32_t aTb = aT[buf], bTb = bT[buf];

        #pragma unroll
        for (int mt = 0; mt < 2; mt++)
            ldsm_x4(aTb + swzA[mt], afr[0][mt]);
        #pragma unroll
        for (int nt2 = 0; nt2 < 2; nt2++) {
            uint32_t rr[4];
            ldsm_x4_t(bTb + swzB[nt2], rr);
            bfr[0][nt2 * 2][0] = rr[0]; bfr[0][nt2 * 2][1] = rr[1];
            bfr[0][nt2 * 2 + 1][0] = rr[2]; bfr[0][nt2 * 2 + 1][1] = rr[3];
        }

        #pragma unroll
        for (int ks = 0; ks < 4; ks++) {
            int cur = ks & 1, nxt = cur ^ 1;
            if (ks < 3) {
                int kk = (ks + 1) * 16;
                #pragma unroll
                for (int mt = 0; mt < 2; mt++)
                    ldsm_x4(aTb + (swzA[mt] ^ (uint32_t)(kk << 1)), afr[nxt][mt]);
                #pragma unroll
                for (int nt2 = 0; nt2 < 2; nt2++) {
                    uint32_t rr[4];
                    ldsm_x4_t(bTb + swzB[nt2] + (uint32_t)(kk << 7), rr);
                    bfr[nxt][nt2 * 2][0] = rr[0]; bfr[nxt][nt2 * 2][1] = rr[1];
                    bfr[nxt][nt2 * 2 + 1][0] = rr[2]; bfr[nxt][nt2 * 2 + 1][1] = rr[3];
                }
            }
            #pragma unroll
            for (int mt = 0; mt < 2; mt++)
                #pragma unroll
                for (int nt = 0; nt < 4; nt++)
                    mma_bf16(c[mt][nt], afr[cur][mt], bfr[cur][nt]);
        }
        __syncthreads();
    }

    // epilogue: bf16 packed stores
    #pragma unroll
    for (int mt = 0; mt < 2; mt++) {
        int row0 = m0 + wm + mt * 16 + (lane >> 2);
        #pragma unroll
        for (int nt = 0; nt < 4; nt++) {
            int col = n0 + wn + nt * 8 + (lane & 3) * 2;
            __nv_bfloat162 v0 = __floats2bfloat162_rn(c[mt][nt][0], c[mt][nt][1]);
            __nv_bfloat162 v1 = __floats2bfloat162_rn(c[mt][nt][2], c[mt][nt][3]);
            *(__nv_bfloat162*)&Oo[(size_t)row0 * D + col] = v0;
            *(__nv_bfloat162*)&Oo[(size_t)(row0 + 8) * D + col] = v1;
        }
    }
}

// ---------------- kernel 4: elu(0.5*(ΣO+h)), row-normalize, +bias ---------
__global__ void __launch_bounds__(256) k_final(const float* __restrict__ bias,
                                               float* __restrict__ out) {
    int tid = threadIdx.x;
    int lane = tid & 31, warp = tid >> 5;
    int i = blockIdx.x * 8 + warp;
    int d0 = lane * 8;
    size_t base = (size_t)i * D + d0;

    float acc[8];
    {
        float4 aA = *(const float4*)&g_h[base];
        float4 aB = *(const float4*)&g_h[base + 4];
        acc[0] = aA.x; acc[1] = aA.y; acc[2] = aA.z; acc[3] = aA.w;
        acc[4] = aB.x; acc[5] = aB.y; acc[6] = aB.z; acc[7] = aB.w;
    }
    #pragma unroll
    for (int z = 0; z < KSPLIT; z++) {
        const __nv_bfloat16* Op = g_Opb + (size_t)z * N * D;
        uint4 v = *(const uint4*)&Op[base];          // 8 bf16
        uint32_t vv[4] = { v.x, v.y, v.z, v.w };
        #pragma unroll
        for (int p = 0; p < 4; p++) {
            float2 f = __bfloat1622float2(*(__nv_bfloat162*)&vv[p]);
            acc[p * 2]     += f.x;
            acc[p * 2 + 1] += f.y;
        }
    }
    float u[8];
    float ss = 0.f;
    #pragma unroll
    for (int k = 0; k < 8; k++) {
        float v = 0.5f * acc[k];
        u[k] = v > 0.f ? v : expm1f(v);
        ss = fmaf(u[k], u[k], ss);
    }
    #pragma unroll
    for (int s = 16; s > 0; s >>= 1) ss += __shfl_xor_sync(0xFFFFFFFFu, ss, s);
    float inv = 1.f / fmaxf(sqrtf(ss), 1e-12f);

    float4 bA = *(const float4*)&bias[d0];
    float4 bB = *(const float4*)&bias[d0 + 4];
    float bb[8] = { bA.x, bA.y, bA.z, bA.w, bB.x, bB.y, bB.z, bB.w };
    float4 rA, rB;
    rA.x = u[0] * inv + bb[0]; rA.y = u[1] * inv + bb[1];
    rA.z = u[2] * inv + bb[2]; rA.w = u[3] * inv + bb[3];
    rB.x = u[4] * inv + bb[4]; rB.y = u[5] * inv + bb[5];
    rB.z = u[6] * inv + bb[6]; rB.w = u[7] * inv + bb[7];
    *(float4*)&out[base] = rA;
    *(float4*)&out[base + 4] = rB;
}

// ---------------- launcher ----------------
extern "C" void kernel_launch(void* const* d_in, const int* in_sizes, int n_in,
                              void* d_out, int out_size) {
    const float* x   = (const float*)d_in[0];
    const int*   adj = (const int*)d_in[1];
    const float* cw  = (const float*)d_in[2];
    const float* cb  = (const float*)d_in[3];
    const float* a   = (const float*)d_in[4];
    const float* bias= (const float*)d_in[5];
    float* out = (float*)d_out;

    k_prep<<<N / 4, D>>>(x, cw, cb, a);
    k_row<<<N, 256>>>(adj);

    int smem_gemm = 3 * (ABYTES + BBYTES);       // 73728
    cudaFuncSetAttribute(k_gemm_mma, cudaFuncAttributeMaxDynamicSharedMemorySize, smem_gemm);
    dim3 grid(D / BN, N / BM, KSPLIT);           // (4, 32, 8) = 1024 CTAs
    k_gemm_mma<<<grid, 256, smem_gemm>>>();

    k_final<<<N / 8, 256>>>(bias, out);
}